// round 13
// baseline (speedup 1.0000x reference)
#include <cuda_runtime.h>

// ---------------------------------------------------------------------------
//   x:  [2, 512, 512] complex (separate real/imag f32 planes)
//   P:  [128, 128] f32;  I: [2, 49, 128, 128] f32;  Ns: [49, 2] int32
//   out: float32 [2, 49, 512, 512] = REAL PART of complex grads (25,690,112)
//
// Fourier-domain restructuring:
//   X = fft2(x) carried unshifted; step k touches only a 128x128 window:
//     X[u0,u1] -= MU*scale_bwd * patch  (0.16)
//   grads[k] = ifft2(ifftshift(Z_k)) * 16, Z_k sparse -> two deferred passes,
//   final pass emits only the real part.
//
// R12->R13: chain = ONE block (1024 thr) per batch; whole 128x128 tile lives
// in smem as separate re/im planes (129-float row stride => conflict-free
// rows AND columns). No grid barriers, no fences, no global ping-pong.
// DIF/DIT pairing (proven in R12) avoids all bit-reversal permute passes.
// ---------------------------------------------------------------------------

#define NOBJ 512
#define MM   128
#define NCH  49
#define NB   2
#define PADF 129                       // floats per smem row (129 % 32 == 1)

__device__ float2 g_tw[256];                         // exp(+2*pi*i*k/512), k<256
__device__ float2 g_xFT[NB * NOBJ * NOBJ];           // 4 MB
__device__ float2 g_patch[NCH * NB * MM * MM];       // 12.8 MB  [kb][r][c]
__device__ float2 g_T[(size_t)NCH * NB * NOBJ * MM]; // 51.4 MB  [kb][t][c]

__device__ __forceinline__ int clampi(int i, int n) {
    return i < 0 ? 0 : (i >= n ? n - 1 : i);
}
__device__ __forceinline__ int brev7(int x) {
    return (int)(__brev((unsigned)x) >> 25);
}

// ---------------------------------------------------------------------------
// warp_fft: permute + DIT on float2 rows, natural->natural (init/grad kernels,
// R10-proven). tw is base-512: exp(+2*pi*i*k/512); INV => +i twiddles.
// ---------------------------------------------------------------------------
template <int L, int LOGL, bool INV>
__device__ __forceinline__ void warp_fft(float2* a, const float2* tw) {
    const int lane = threadIdx.x & 31;
    constexpr int NPT = L / 32;
    float2 v[NPT];
#pragma unroll
    for (int q = 0; q < NPT; q++) {
        int idx = lane + (q << 5);
        int r = (int)(__brev((unsigned)idx) >> (32 - LOGL));
        v[q] = a[r];
    }
    __syncwarp();
#pragma unroll
    for (int q = 0; q < NPT; q++) a[lane + (q << 5)] = v[q];
    __syncwarp();
#pragma unroll
    for (int s = 1; s <= LOGL; s++) {
        const int half = 1 << (s - 1);
#pragma unroll
        for (int t = 0; t < (L >> 6); t++) {
            int j = lane + (t << 5);
            int pos = j & (half - 1);
            int i0 = ((j >> (s - 1)) << s) + pos;
            int i1 = i0 + half;
            float2 w = tw[pos << (9 - s)];
            float wy = INV ? w.y : -w.y;
            float2 x0 = a[i0], x1 = a[i1];
            float tr = w.x * x1.x - wy * x1.y;
            float ti = w.x * x1.y + wy * x1.x;
            a[i0] = make_float2(x0.x + tr, x0.y + ti);
            a[i1] = make_float2(x0.x - tr, x0.y - ti);
        }
        __syncwarp();
    }
}

// ---------------------------------------------------------------------------
// Plane FFTs: 4 independent 128-pt transforms per warp on float re/im planes.
// Transform rr: element i at offset b0 + rr*dstep + i*estr.
// DIF: natural in -> bitrev out.  DIT: bitrev in -> natural out.
// (Identical butterfly/twiddle schedule to R12's float2 versions, which
//  passed correctness.)
// ---------------------------------------------------------------------------
template <bool INV>
__device__ __forceinline__ void fft128_dif4p(float* re, float* im,
                                             int b0, int dstep, int estr,
                                             const float2* tw) {
    const int lane = threadIdx.x & 31;
#pragma unroll
    for (int s = 7; s >= 1; s--) {
        const int half = 1 << (s - 1);
#pragma unroll
        for (int t = 0; t < 2; t++) {
            const int j = lane + (t << 5);
            const int pos = j & (half - 1);
            const int i0 = ((j >> (s - 1)) << s) + pos;
            const int i1 = i0 + half;
            const float2 w = tw[pos << (9 - s)];
            const float wy = INV ? w.y : -w.y;
#pragma unroll
            for (int rr = 0; rr < 4; rr++) {
                const int o0 = b0 + rr * dstep + i0 * estr;
                const int o1 = b0 + rr * dstep + i1 * estr;
                float x0r = re[o0], x0i = im[o0];
                float x1r = re[o1], x1i = im[o1];
                float dr = x0r - x1r, di = x0i - x1i;
                re[o0] = x0r + x1r; im[o0] = x0i + x1i;
                re[o1] = w.x * dr - wy * di;
                im[o1] = w.x * di + wy * dr;
            }
        }
        __syncwarp();
    }
}

template <bool INV>
__device__ __forceinline__ void fft128_dit4p(float* re, float* im,
                                             int b0, int dstep, int estr,
                                             const float2* tw) {
    const int lane = threadIdx.x & 31;
#pragma unroll
    for (int s = 1; s <= 7; s++) {
        const int half = 1 << (s - 1);
#pragma unroll
        for (int t = 0; t < 2; t++) {
            const int j = lane + (t << 5);
            const int pos = j & (half - 1);
            const int i0 = ((j >> (s - 1)) << s) + pos;
            const int i1 = i0 + half;
            const float2 w = tw[pos << (9 - s)];
            const float wy = INV ? w.y : -w.y;
#pragma unroll
            for (int rr = 0; rr < 4; rr++) {
                const int o0 = b0 + rr * dstep + i0 * estr;
                const int o1 = b0 + rr * dstep + i1 * estr;
                float x0r = re[o0], x0i = im[o0];
                float x1r = re[o1], x1i = im[o1];
                float tr = w.x * x1r - wy * x1i;
                float ti = w.x * x1i + wy * x1r;
                re[o0] = x0r + tr; im[o0] = x0i + ti;
                re[o1] = x0r - tr; im[o1] = x0i - ti;
            }
        }
        __syncwarp();
    }
}

__global__ void k_init_tw() {
    int k = threadIdx.x;  // 256 threads
    double ang = 6.283185307179586476925286766559 * (double)k / 512.0;
    g_tw[k] = make_float2((float)cos(ang), (float)sin(ang));
}

// fft2(x) pass 1: axis-1 transforms. 128 blocks x 256 threads (8 warps/cols).
__global__ void __launch_bounds__(256) k_init_cols(const float* __restrict__ xr,
                                                   const float* __restrict__ xi,
                                                   int nx) {
    __shared__ float2 sm[8 * 520 + 256];
    float2* tw = sm + 8 * 520;
    int tid = threadIdx.x, w = tid >> 5, lane = tid & 31;
    tw[tid] = g_tw[tid];
    __syncthreads();
    int b = blockIdx.x >> 6;
    int c0 = (blockIdx.x & 63) << 3;
    int col = c0 + w;
    float2* a = sm + w * 520;
#pragma unroll
    for (int q = 0; q < 16; q++) {
        int j = lane + (q << 5);
        int idx = clampi(b * 262144 + j * 512 + col, nx);
        a[j] = make_float2(xr[idx], xi[idx]);
    }
    __syncwarp();
    warp_fft<512, 9, false>(a, tw);
    __syncthreads();
    for (int e = tid; e < 4096; e += 256) {      // transposed coalesced store
        int t = e >> 3, ww = e & 7;
        g_T[((size_t)b * 512 + t) * 512 + c0 + ww] = sm[ww * 520 + t];
    }
}

// fft2(x) pass 2: axis-2 transforms -> g_xFT (unshifted). 128 blocks x 256.
__global__ void __launch_bounds__(256) k_init_rows() {
    __shared__ float2 sm[8 * 520 + 256];
    float2* tw = sm + 8 * 520;
    int tid = threadIdx.x, w = tid >> 5, lane = tid & 31;
    tw[tid] = g_tw[tid];
    __syncthreads();
    int b = blockIdx.x >> 6;
    int f = ((blockIdx.x & 63) << 3) + w;
    float2* a = sm + w * 520;
    const float2* src = g_T + ((size_t)b * 512 + f) * 512;
#pragma unroll
    for (int q = 0; q < 16; q++) { int u = lane + (q << 5); a[u] = src[u]; }
    __syncwarp();
    warp_fft<512, 9, false>(a, tw);
    float2* dst = g_xFT + (size_t)b * 262144 + (size_t)f * 512;
#pragma unroll
    for (int q = 0; q < 16; q++) { int u = lane + (q << 5); dst[u] = a[u]; }
}

// ---------------------------------------------------------------------------
// Fused persistent chain: grid = 2 (one block per batch), 1024 threads.
// Whole step tile in smem planes; __syncthreads-only synchronization.
// ---------------------------------------------------------------------------
__global__ void __launch_bounds__(1024, 1) k_chain(const float* __restrict__ P,
                                                   const float* __restrict__ I,
                                                   const int* __restrict__ Ns) {
    extern __shared__ float smem[];
    float* re = smem;                   // [128][PADF]
    float* im = smem + 128 * PADF;      // [128][PADF]
    __shared__ float2 tw[256];
    int tid = threadIdx.x, w = tid >> 5;
    if (tid < 256) tw[tid] = g_tw[tid];
    __syncthreads();
    int b = blockIdx.x;
    float2* xft = g_xFT + (size_t)b * 262144;
    const float sA = 1.0f / 262144.0f;  // (1/128^2) * scale_fwd(=1/16)

    for (int k = 0; k < NCH; k++) {
        int kxl = 192 + Ns[2 * k];
        int kyl = 192 + Ns[2 * k + 1];

        // load window * P (ifftshift folded): natural (j0, j1)
        for (int e = tid; e < 16384; e += 1024) {
            int j0 = e >> 7, j1 = e & 127;
            int r = (j0 + 64) & 127, c = (j1 + 64) & 127;
            int u0 = (kxl + r + 256) & 511;
            int u1 = (kyl + c + 256) & 511;
            float2 xv = xft[u0 * 512 + u1];
            float p = P[r * 128 + c];
            re[j0 * PADF + j1] = xv.x * p;
            im[j0 * PADF + j1] = xv.y * p;
        }
        __syncthreads();
        // row IFFT (DIF): j1 natural -> bitrev(n1)
        fft128_dif4p<true>(re, im, w * PADF, 32 * PADF, 1, tw);
        __syncthreads();
        // col IFFT (DIF): j0 natural -> bitrev(n0)
        fft128_dif4p<true>(re, im, w, 32, PADF, tw);
        __syncthreads();
        // nonlinearity at physical (p0, p1) = (brev(n0), brev(n1))
        {
            const float* Ik = I + ((size_t)b * NCH + k) * 16384;
            for (int e = tid; e < 16384; e += 1024) {
                int p0 = e >> 7, p1 = e & 127;
                int n0 = brev7(p0), n1 = brev7(p1);
                float vr = re[p0 * PADF + p1] * sA;
                float vi = im[p0 * PADF + p1] * sA;
                float m = vr * vr + vi * vi - Ik[n0 * 128 + n1];
                re[p0 * PADF + p1] = m * vr;
                im[p0 * PADF + p1] = m * vi;
            }
        }
        __syncthreads();
        // col FFT (DIT): bitrev -> natural m0
        fft128_dit4p<false>(re, im, w, 32, PADF, tw);
        __syncthreads();
        // row FFT (DIT): bitrev -> natural m1
        fft128_dit4p<false>(re, im, w * PADF, 32 * PADF, 1, tw);
        __syncthreads();
        // patch = fftshift(F) * P; store patch; update xFT window
        {
            int kb = k * NB + b;
            float2* patch = g_patch + (size_t)kb * 16384;
            for (int e = tid; e < 16384; e += 1024) {
                int m0 = e >> 7, m1 = e & 127;
                int r = (m0 + 64) & 127, c = (m1 + 64) & 127;
                float p = P[r * 128 + c];
                float pr = re[m0 * PADF + m1] * p;
                float pi = im[m0 * PADF + m1] * p;
                patch[r * 128 + c] = make_float2(pr, pi);
                int u0 = (kxl + r + 256) & 511;
                int u1 = (kyl + c + 256) & 511;
                float2 xv = xft[u0 * 512 + u1];
                xft[u0 * 512 + u1] = make_float2(xv.x - 0.16f * pr,
                                                 xv.y - 0.16f * pi);
            }
        }
        __syncthreads();
    }
}

// Grad pass 1: sparse axis-1 IFFT (128 nonzero rows -> 512). 1568 blocks x 256.
__global__ void __launch_bounds__(256) k_grad1(const int* __restrict__ Ns, int nns) {
    __shared__ float2 sm[8 * 520 + 256];
    float2* tw = sm + 8 * 520;
    int tid = threadIdx.x, w = tid >> 5, lane = tid & 31;
    tw[tid] = g_tw[tid];
    __syncthreads();
    int kb = blockIdx.x >> 4;
    int k = kb >> 1;
    int c0 = (blockIdx.x & 15) << 3;
    int c = c0 + w;
    int kxl = 192 + Ns[clampi(2 * k, nns)];
    float2* a = sm + w * 520;
#pragma unroll
    for (int q = 0; q < 16; q++) a[lane + (q << 5)] = make_float2(0.f, 0.f);
    __syncwarp();
    for (int r = lane; r < 128; r += 32) {
        int u0 = (kxl + r + 256) & 511;
        a[u0] = g_patch[(size_t)kb * 16384 + r * 128 + c];
    }
    __syncwarp();
    warp_fft<512, 9, true>(a, tw);
    __syncthreads();
    for (int e = tid; e < 4096; e += 256) {
        int t = e >> 3, ww = e & 7;
        g_T[((size_t)kb * 512 + t) * 128 + c0 + ww] = sm[ww * 520 + t];
    }
}

// Grad pass 2: sparse axis-2 IFFT -> REAL PART only, scaled, to output.
__global__ void __launch_bounds__(256) k_grad2(const int* __restrict__ Ns, int nns,
                                               float* __restrict__ outf,
                                               int n_out) {
    __shared__ float2 sm[8 * 520 + 256];
    float2* tw = sm + 8 * 520;
    int tid = threadIdx.x, w = tid >> 5, lane = tid & 31;
    tw[tid] = g_tw[tid];
    __syncthreads();
    int kb = blockIdx.x >> 6;
    int t = ((blockIdx.x & 63) << 3) + w;
    int k = kb >> 1, b = kb & 1;
    int kyl = 192 + Ns[clampi(2 * k + 1, nns)];
    float2* a = sm + w * 520;
#pragma unroll
    for (int q = 0; q < 16; q++) a[lane + (q << 5)] = make_float2(0.f, 0.f);
    __syncwarp();
    const float2* src = g_T + ((size_t)kb * 512 + t) * 128;
    for (int c = lane; c < 128; c += 32) {
        int u1 = (kyl + c + 256) & 511;
        a[u1] = src[c];
    }
    __syncwarp();
    warp_fft<512, 9, true>(a, tw);
    const float s = 1.0f / 16384.0f;        // (1/512^2) * scale_bwd(=16)
    long long base = (((long long)b * NCH + k) * 512 + t) * 512;
#pragma unroll
    for (int q = 0; q < 16; q++) {
        int u = lane + (q << 5);
        long long idx = base + u;           // float32 element index
        if (idx < (long long)n_out) {
            outf[idx] = a[u].x * s;         // REAL part only
        }
    }
}

// ---------------------------------------------------------------------------
extern "C" void kernel_launch(void* const* d_in, const int* in_sizes, int n_in,
                              void* d_out, int out_size) {
    // Bind by element count. The two 524288 buffers: FIRST = x_real,
    // SECOND = x_imag (verified passing in R10/R11/R12).
    const float *xr = nullptr, *xi = nullptr, *P = nullptr, *I = nullptr;
    const int* Ns = nullptr;
    int nx = 0, nns = 0;
    for (int i = 0; i < n_in; i++) {
        int sz = in_sizes[i];
        if (sz == 524288) {
            if (!xr) { xr = (const float*)d_in[i]; nx = sz; }
            else if (!xi) xi = (const float*)d_in[i];
        } else if (sz == 16384) { P = (const float*)d_in[i]; }
        else if (sz == 1605632) { I = (const float*)d_in[i]; }
        else if (sz == 98)      { Ns = (const int*)d_in[i]; nns = sz; }
    }
    if (!xr || !xi || !P || !I || !Ns) return;
    float* outf = (float*)d_out;

    const int chain_smem = 2 * 128 * PADF * sizeof(float);  // 132096 B
    cudaFuncSetAttribute(k_chain, cudaFuncAttributeMaxDynamicSharedMemorySize,
                         chain_smem);

    k_init_tw<<<1, 256>>>();
    k_init_cols<<<128, 256>>>(xr, xi, nx);
    k_init_rows<<<128, 256>>>();
    k_chain<<<2, 1024, chain_smem>>>(P, I, Ns);
    k_grad1<<<1568, 256>>>(Ns, nns);
    k_grad2<<<6272, 256>>>(Ns, nns, outf, out_size);
}

// round 14
// speedup vs baseline: 2.7728x; 2.7728x over previous
#include <cuda_runtime.h>

// ---------------------------------------------------------------------------
//   x:  [2, 512, 512] complex (separate real/imag f32 planes)
//   P:  [128, 128] f32;  I: [2, 49, 128, 128] f32;  Ns: [49, 2] int32
//   out: float32 [2, 49, 512, 512] = REAL PART of complex grads (25,690,112)
//
// Fourier-domain restructuring:
//   X = fft2(x) carried unshifted; step k touches only a 128x128 window:
//     X[u0,u1] -= MU*scale_bwd * patch  (0.16)
//   grads[k] = ifft2(ifftshift(Z_k)) * 16, Z_k sparse -> two deferred passes,
//   final pass emits only the real part.
//
// R13->R14: chain = R11's proven 3-phase global ping-pong, but with 8 blocks
// per batch in ONE CLUSTER (grid 16 = 2 clusters of 8), 512 threads/block,
// and hardware barrier.cluster sync (~380cyc, release/acquire + L1 flush)
// instead of the software atomic barrier (~5us/phase overhead in R11).
// ---------------------------------------------------------------------------

#define NOBJ 512
#define MM   128
#define NCH  49
#define NB   2
#define CL   8        // blocks per cluster (= per batch)

__device__ float2 g_tw[256];                         // exp(+2*pi*i*k/512), k<256
__device__ float2 g_xFT[NB * NOBJ * NOBJ];           // 4 MB
__device__ float2 g_patch[NCH * NB * MM * MM];       // 12.8 MB  [kb][r][c]
__device__ float2 g_T[(size_t)NCH * NB * NOBJ * MM]; // 51.4 MB  [kb][t][c]
__device__ float2 g_W[NB * MM * MM];                 // step ping  [b][n1][j0]
__device__ float2 g_W2[NB * MM * MM];                // step pong  [b][m0][n1]

__device__ __forceinline__ int clampi(int i, int n) {
    return i < 0 ? 0 : (i >= n ? n - 1 : i);
}

#define CLUSTER_ARRIVE() asm volatile("barrier.cluster.arrive.aligned;" ::: "memory")
#define CLUSTER_WAIT()   asm volatile("barrier.cluster.wait.aligned;" ::: "memory")

// ---------------------------------------------------------------------------
// warp_fft: permute + DIT on float2 rows, natural->natural (R10-proven).
// tw is base-512: exp(+2*pi*i*k/512); INV => +i twiddles. No normalization.
// ---------------------------------------------------------------------------
template <int L, int LOGL, bool INV>
__device__ __forceinline__ void warp_fft(float2* a, const float2* tw) {
    const int lane = threadIdx.x & 31;
    constexpr int NPT = L / 32;
    float2 v[NPT];
#pragma unroll
    for (int q = 0; q < NPT; q++) {
        int idx = lane + (q << 5);
        int r = (int)(__brev((unsigned)idx) >> (32 - LOGL));
        v[q] = a[r];
    }
    __syncwarp();
#pragma unroll
    for (int q = 0; q < NPT; q++) a[lane + (q << 5)] = v[q];
    __syncwarp();
#pragma unroll
    for (int s = 1; s <= LOGL; s++) {
        const int half = 1 << (s - 1);
#pragma unroll
        for (int t = 0; t < (L >> 6); t++) {
            int j = lane + (t << 5);
            int pos = j & (half - 1);
            int i0 = ((j >> (s - 1)) << s) + pos;
            int i1 = i0 + half;
            float2 w = tw[pos << (9 - s)];
            float wy = INV ? w.y : -w.y;
            float2 x0 = a[i0], x1 = a[i1];
            float tr = w.x * x1.x - wy * x1.y;
            float ti = w.x * x1.y + wy * x1.x;
            a[i0] = make_float2(x0.x + tr, x0.y + ti);
            a[i1] = make_float2(x0.x - tr, x0.y - ti);
        }
        __syncwarp();
    }
}

__global__ void k_init_tw() {
    int k = threadIdx.x;  // 256 threads
    double ang = 6.283185307179586476925286766559 * (double)k / 512.0;
    g_tw[k] = make_float2((float)cos(ang), (float)sin(ang));
}

// fft2(x) pass 1: axis-1 transforms. 128 blocks x 256 threads (8 warps/cols).
__global__ void __launch_bounds__(256) k_init_cols(const float* __restrict__ xr,
                                                   const float* __restrict__ xi,
                                                   int nx) {
    __shared__ float2 sm[8 * 520 + 256];
    float2* tw = sm + 8 * 520;
    int tid = threadIdx.x, w = tid >> 5, lane = tid & 31;
    tw[tid] = g_tw[tid];
    __syncthreads();
    int b = blockIdx.x >> 6;
    int c0 = (blockIdx.x & 63) << 3;
    int col = c0 + w;
    float2* a = sm + w * 520;
#pragma unroll
    for (int q = 0; q < 16; q++) {
        int j = lane + (q << 5);
        int idx = clampi(b * 262144 + j * 512 + col, nx);
        a[j] = make_float2(xr[idx], xi[idx]);
    }
    __syncwarp();
    warp_fft<512, 9, false>(a, tw);
    __syncthreads();
    for (int e = tid; e < 4096; e += 256) {      // transposed coalesced store
        int t = e >> 3, ww = e & 7;
        g_T[((size_t)b * 512 + t) * 512 + c0 + ww] = sm[ww * 520 + t];
    }
}

// fft2(x) pass 2: axis-2 transforms -> g_xFT (unshifted). 128 blocks x 256.
__global__ void __launch_bounds__(256) k_init_rows() {
    __shared__ float2 sm[8 * 520 + 256];
    float2* tw = sm + 8 * 520;
    int tid = threadIdx.x, w = tid >> 5, lane = tid & 31;
    tw[tid] = g_tw[tid];
    __syncthreads();
    int b = blockIdx.x >> 6;
    int f = ((blockIdx.x & 63) << 3) + w;
    float2* a = sm + w * 520;
    const float2* src = g_T + ((size_t)b * 512 + f) * 512;
#pragma unroll
    for (int q = 0; q < 16; q++) { int u = lane + (q << 5); a[u] = src[u]; }
    __syncwarp();
    warp_fft<512, 9, false>(a, tw);
    float2* dst = g_xFT + (size_t)b * 262144 + (size_t)f * 512;
#pragma unroll
    for (int q = 0; q < 16; q++) { int u = lane + (q << 5); dst[u] = a[u]; }
}

// ---------------------------------------------------------------------------
// Chain: cluster of 8 blocks per batch, 512 threads (16 warps = 16 rows/cols
// per block, one transform per warp). 3 cluster barriers per step.
// ---------------------------------------------------------------------------
__global__ void __launch_bounds__(512, 1) __cluster_dims__(CL, 1, 1)
k_chain(const float* __restrict__ P, const float* __restrict__ I,
        const int* __restrict__ Ns) {
    __shared__ float2 sm[16 * 132];
    __shared__ float2 tw[256];
    int tid = threadIdx.x, w = tid >> 5, lane = tid & 31;
    if (tid < 256) tw[tid] = g_tw[tid];
    __syncthreads();
    int b = blockIdx.x >> 3;          // cluster index = batch
    int blk = blockIdx.x & 7;         // rank within cluster
    int rowbase = blk << 4;           // 16 rows/cols owned by this block
    float2* a = sm + w * 132;
    float2* xft = g_xFT + (size_t)b * 262144;
    float2* Wb = g_W + (size_t)b * 16384;
    float2* W2b = g_W2 + (size_t)b * 16384;
    const float sA = 1.0f / 262144.0f;  // (1/128^2) * scale_fwd(=1/16)

    for (int k = 0; k < NCH; k++) {
        int kxl = 192 + Ns[2 * k];
        int kyl = 192 + Ns[2 * k + 1];

        // ---- phase 1: window*P (ifftshift folded) -> row IFFT -> g_W^T ----
        {
            int j0 = rowbase + w;
            int r = (j0 + 64) & 127;
            int u0 = (kxl + r + 256) & 511;
            const float2* xrow = xft + (size_t)u0 * 512;
            const float* prow = P + r * 128;
#pragma unroll
            for (int q = 0; q < 4; q++) {
                int j1 = lane + (q << 5);
                int c = (j1 + 64) & 127;
                int u1 = (kyl + c + 256) & 511;
                float2 xv = __ldcg(&xrow[u1]);
                float p = prow[c];
                a[j1] = make_float2(xv.x * p, xv.y * p);
            }
            __syncwarp();
            warp_fft<128, 7, true>(a, tw);
            __syncthreads();
            for (int e = tid; e < 2048; e += 512) {   // g_W[n1][j0]
                int n1 = e >> 4, rl = e & 15;
                Wb[n1 * 128 + rowbase + rl] = sm[rl * 132 + n1];
            }
        }
        CLUSTER_ARRIVE(); CLUSTER_WAIT();

        // ---- phase 2: col IFFT -> nonlinearity -> col FFT -> g_W2^T ----
        {
            int n1 = rowbase + w;
            const float2* src = Wb + (size_t)n1 * 128;
#pragma unroll
            for (int q = 0; q < 4; q++) { int u = lane + (q << 5); a[u] = __ldcg(&src[u]); }
            __syncwarp();
            warp_fft<128, 7, true>(a, tw);
            const float* Ik = I + ((size_t)b * NCH + k) * 16384;
#pragma unroll
            for (int q = 0; q < 4; q++) {
                int n0 = lane + (q << 5);
                float2 v = a[n0];
                float vr = v.x * sA, vi = v.y * sA;
                float m = vr * vr + vi * vi - Ik[n0 * 128 + n1];
                a[n0] = make_float2(m * vr, m * vi);
            }
            __syncwarp();
            warp_fft<128, 7, false>(a, tw);
            __syncthreads();
            for (int e = tid; e < 2048; e += 512) {   // g_W2[m0][n1]
                int m0 = e >> 4, rl = e & 15;
                W2b[m0 * 128 + rowbase + rl] = sm[rl * 132 + m0];
            }
        }
        CLUSTER_ARRIVE(); CLUSTER_WAIT();

        // ---- phase 3: row FFT -> patch = fftshift(F)*P; update xFT ----
        {
            int m0 = rowbase + w;
            const float2* src = W2b + (size_t)m0 * 128;
#pragma unroll
            for (int q = 0; q < 4; q++) { int u = lane + (q << 5); a[u] = __ldcg(&src[u]); }
            __syncwarp();
            warp_fft<128, 7, false>(a, tw);
            int r = (m0 + 64) & 127;
            int u0 = (kxl + r + 256) & 511;
            int kb = k * NB + b;
            float2* patch_row = g_patch + (size_t)kb * 16384 + r * 128;
            float2* xrow = xft + (size_t)u0 * 512;
            const float* prow = P + r * 128;
#pragma unroll
            for (int q = 0; q < 4; q++) {
                int m1 = lane + (q << 5);
                int c = (m1 + 64) & 127;
                float p = prow[c];
                float2 f = a[m1];
                float2 patch = make_float2(f.x * p, f.y * p);
                patch_row[c] = patch;
                int u1 = (kyl + c + 256) & 511;
                float2 xv = __ldcg(&xrow[u1]);
                xrow[u1] = make_float2(xv.x - 0.16f * patch.x,
                                       xv.y - 0.16f * patch.y);
            }
        }
        CLUSTER_ARRIVE(); CLUSTER_WAIT();
    }
}

// Grad pass 1: sparse axis-1 IFFT (128 nonzero rows -> 512). 1568 blocks x 256.
__global__ void __launch_bounds__(256) k_grad1(const int* __restrict__ Ns, int nns) {
    __shared__ float2 sm[8 * 520 + 256];
    float2* tw = sm + 8 * 520;
    int tid = threadIdx.x, w = tid >> 5, lane = tid & 31;
    tw[tid] = g_tw[tid];
    __syncthreads();
    int kb = blockIdx.x >> 4;
    int k = kb >> 1;
    int c0 = (blockIdx.x & 15) << 3;
    int c = c0 + w;
    int kxl = 192 + Ns[clampi(2 * k, nns)];
    float2* a = sm + w * 520;
#pragma unroll
    for (int q = 0; q < 16; q++) a[lane + (q << 5)] = make_float2(0.f, 0.f);
    __syncwarp();
    for (int r = lane; r < 128; r += 32) {
        int u0 = (kxl + r + 256) & 511;
        a[u0] = g_patch[(size_t)kb * 16384 + r * 128 + c];
    }
    __syncwarp();
    warp_fft<512, 9, true>(a, tw);
    __syncthreads();
    for (int e = tid; e < 4096; e += 256) {
        int t = e >> 3, ww = e & 7;
        g_T[((size_t)kb * 512 + t) * 128 + c0 + ww] = sm[ww * 520 + t];
    }
}

// Grad pass 2: sparse axis-2 IFFT -> REAL PART only, scaled, to output.
__global__ void __launch_bounds__(256) k_grad2(const int* __restrict__ Ns, int nns,
                                               float* __restrict__ outf,
                                               int n_out) {
    __shared__ float2 sm[8 * 520 + 256];
    float2* tw = sm + 8 * 520;
    int tid = threadIdx.x, w = tid >> 5, lane = tid & 31;
    tw[tid] = g_tw[tid];
    __syncthreads();
    int kb = blockIdx.x >> 6;
    int t = ((blockIdx.x & 63) << 3) + w;
    int k = kb >> 1, b = kb & 1;
    int kyl = 192 + Ns[clampi(2 * k + 1, nns)];
    float2* a = sm + w * 520;
#pragma unroll
    for (int q = 0; q < 16; q++) a[lane + (q << 5)] = make_float2(0.f, 0.f);
    __syncwarp();
    const float2* src = g_T + ((size_t)kb * 512 + t) * 128;
    for (int c = lane; c < 128; c += 32) {
        int u1 = (kyl + c + 256) & 511;
        a[u1] = src[c];
    }
    __syncwarp();
    warp_fft<512, 9, true>(a, tw);
    const float s = 1.0f / 16384.0f;        // (1/512^2) * scale_bwd(=16)
    long long base = (((long long)b * NCH + k) * 512 + t) * 512;
#pragma unroll
    for (int q = 0; q < 16; q++) {
        int u = lane + (q << 5);
        long long idx = base + u;           // float32 element index
        if (idx < (long long)n_out) {
            outf[idx] = a[u].x * s;         // REAL part only
        }
    }
}

// ---------------------------------------------------------------------------
extern "C" void kernel_launch(void* const* d_in, const int* in_sizes, int n_in,
                              void* d_out, int out_size) {
    // Bind by element count. The two 524288 buffers: FIRST = x_real,
    // SECOND = x_imag (verified passing R10-R13).
    const float *xr = nullptr, *xi = nullptr, *P = nullptr, *I = nullptr;
    const int* Ns = nullptr;
    int nx = 0, nns = 0;
    for (int i = 0; i < n_in; i++) {
        int sz = in_sizes[i];
        if (sz == 524288) {
            if (!xr) { xr = (const float*)d_in[i]; nx = sz; }
            else if (!xi) xi = (const float*)d_in[i];
        } else if (sz == 16384) { P = (const float*)d_in[i]; }
        else if (sz == 1605632) { I = (const float*)d_in[i]; }
        else if (sz == 98)      { Ns = (const int*)d_in[i]; nns = sz; }
    }
    if (!xr || !xi || !P || !I || !Ns) return;
    float* outf = (float*)d_out;

    k_init_tw<<<1, 256>>>();
    k_init_cols<<<128, 256>>>(xr, xi, nx);
    k_init_rows<<<128, 256>>>();
    k_chain<<<NB * CL, 512>>>(P, I, Ns);      // 2 clusters of 8 blocks
    k_grad1<<<1568, 256>>>(Ns, nns);
    k_grad2<<<6272, 256>>>(Ns, nns, outf, out_size);
}

// round 15
// speedup vs baseline: 4.0497x; 1.4605x over previous
#include <cuda_runtime.h>

// ---------------------------------------------------------------------------
//   x:  [2, 512, 512] complex (separate real/imag f32 planes)
//   P:  [128, 128] f32;  I: [2, 49, 128, 128] f32;  Ns: [49, 2] int32
//   out: float32 [2, 49, 512, 512] = REAL PART of complex grads (25,690,112)
//
// Fourier-domain restructuring:
//   X = fft2(x) carried unshifted; step k touches only a 128x128 window:
//     X[u0,u1] -= MU*scale_bwd * patch  (0.16)
//   grads[k] = ifft2(ifftshift(Z_k)) * 16, Z_k sparse -> two deferred passes.
//
// R14->R15: chain FFTs move from shared memory into REGISTERS (4 float2 per
// lane) with shuffle butterflies; twiddles preloaded into 7 lane registers.
// smem used only for inter-phase transposes (coalesced). I pre-transposed +
// bit-reversed once (g_It) so the nonlinearity gather is coalesced.
// Cluster-barrier phase structure identical to R14 (passing).
// ---------------------------------------------------------------------------

#define NOBJ 512
#define MM   128
#define NCH  49
#define NB   2
#define CL   8        // blocks per cluster (= per batch)

__device__ float2 g_tw[256];                         // exp(+2*pi*i*k/512), k<256
__device__ float2 g_xFT[NB * NOBJ * NOBJ];           // 4 MB
__device__ float2 g_patch[NCH * NB * MM * MM];       // 12.8 MB  [kb][r][c]
__device__ float2 g_T[(size_t)NCH * NB * NOBJ * MM]; // 51.4 MB  [kb][t][c]
__device__ float2 g_W[NB * MM * MM];                 // step ping  [b][n1][j0]
__device__ float2 g_W2[NB * MM * MM];                // step pong  [b][m0][n1]
__device__ float  g_It[(size_t)NB * NCH * MM * MM];  // 6.4 MB: I transposed+brev

__device__ __forceinline__ int clampi(int i, int n) {
    return i < 0 ? 0 : (i >= n ? n - 1 : i);
}
__device__ __forceinline__ int brev7(int x) {
    return (int)(__brev((unsigned)x) >> 25);
}

#define CLUSTER_SYNC() do { \
    asm volatile("barrier.cluster.arrive.aligned;" ::: "memory"); \
    asm volatile("barrier.cluster.wait.aligned;" ::: "memory"); } while (0)

// ---------------------------------------------------------------------------
// Register-resident 128-pt FFT per warp: element e = q*32+lane in v[q].
// DIF: natural in -> bitrev out.  DIT: bitrev in -> natural out.
// Same butterfly schedule + twiddle indexing as R12's smem version (proven).
// T[0]=tw[lane*4] T[1]=tw[(lane+32)*4] T[2]=tw[lane*8] T[3]=tw[(lane&15)*16]
// T[4]=tw[(lane&7)*32] T[5]=tw[(lane&3)*64] T[6]=tw[(lane&1)*128]
// INV => +i twiddles (inverse), no normalization.
// ---------------------------------------------------------------------------
template <bool INV>
__device__ __forceinline__ void dif_bfly(float2& x0, float2& x1, float2 w) {
    float wy = INV ? w.y : -w.y;
    float dx = x0.x - x1.x, dy = x0.y - x1.y;
    x0.x += x1.x; x0.y += x1.y;
    x1.x = w.x * dx - wy * dy;
    x1.y = w.x * dy + wy * dx;
}
template <bool INV>
__device__ __forceinline__ void dit_bfly(float2& x0, float2& x1, float2 w) {
    float wy = INV ? w.y : -w.y;
    float tx = w.x * x1.x - wy * x1.y;
    float ty = w.x * x1.y + wy * x1.x;
    x1.x = x0.x - tx; x1.y = x0.y - ty;
    x0.x += tx; x0.y += ty;
}
template <bool INV>
__device__ __forceinline__ void dif_shfl(float2 v[4], int half, float2 w, int lane) {
    float wy = INV ? w.y : -w.y;
    bool up = (lane & half) == 0;
#pragma unroll
    for (int q = 0; q < 4; q++) {
        float ox = __shfl_xor_sync(0xffffffffu, v[q].x, half);
        float oy = __shfl_xor_sync(0xffffffffu, v[q].y, half);
        float ax = v[q].x + ox, ay = v[q].y + oy;          // i0 result
        float dx = ox - v[q].x, dy = oy - v[q].y;          // x0 - x1
        float bx = w.x * dx - wy * dy, by = w.x * dy + wy * dx;  // i1 result
        v[q].x = up ? ax : bx;
        v[q].y = up ? ay : by;
    }
}
template <bool INV>
__device__ __forceinline__ void dit_shfl(float2 v[4], int half, float2 w, int lane) {
    float wy = INV ? w.y : -w.y;
    bool up = (lane & half) == 0;
#pragma unroll
    for (int q = 0; q < 4; q++) {
        float ox = __shfl_xor_sync(0xffffffffu, v[q].x, half);
        float oy = __shfl_xor_sync(0xffffffffu, v[q].y, half);
        float sx = up ? ox : v[q].x;          // multiply x1 by w
        float sy = up ? oy : v[q].y;
        float tx = w.x * sx - wy * sy;
        float ty = w.x * sy + wy * sx;
        float rx = up ? (v[q].x + tx) : (ox - tx);
        float ry = up ? (v[q].y + ty) : (oy - ty);
        v[q].x = rx; v[q].y = ry;
    }
}
template <bool INV>
__device__ __forceinline__ void rdif128(float2 v[4], const float2* T, int lane) {
    dif_bfly<INV>(v[0], v[2], T[0]);     // s=7
    dif_bfly<INV>(v[1], v[3], T[1]);
    dif_bfly<INV>(v[0], v[1], T[2]);     // s=6
    dif_bfly<INV>(v[2], v[3], T[2]);
    dif_shfl<INV>(v, 16, T[3], lane);    // s=5
    dif_shfl<INV>(v, 8,  T[4], lane);    // s=4
    dif_shfl<INV>(v, 4,  T[5], lane);    // s=3
    dif_shfl<INV>(v, 2,  T[6], lane);    // s=2
    dif_shfl<INV>(v, 1,  make_float2(1.f, 0.f), lane);  // s=1
}
template <bool INV>
__device__ __forceinline__ void rdit128(float2 v[4], const float2* T, int lane) {
    dit_shfl<INV>(v, 1,  make_float2(1.f, 0.f), lane);  // s=1
    dit_shfl<INV>(v, 2,  T[6], lane);    // s=2
    dit_shfl<INV>(v, 4,  T[5], lane);    // s=3
    dit_shfl<INV>(v, 8,  T[4], lane);    // s=4
    dit_shfl<INV>(v, 16, T[3], lane);    // s=5
    dit_bfly<INV>(v[0], v[1], T[2]);     // s=6
    dit_bfly<INV>(v[2], v[3], T[2]);
    dit_bfly<INV>(v[0], v[2], T[0]);     // s=7
    dit_bfly<INV>(v[1], v[3], T[1]);
}

// ---------------------------------------------------------------------------
// warp_fft (smem, natural->natural) for init/grad kernels — R10-proven.
// ---------------------------------------------------------------------------
template <int L, int LOGL, bool INV>
__device__ __forceinline__ void warp_fft(float2* a, const float2* tw) {
    const int lane = threadIdx.x & 31;
    constexpr int NPT = L / 32;
    float2 v[NPT];
#pragma unroll
    for (int q = 0; q < NPT; q++) {
        int idx = lane + (q << 5);
        int r = (int)(__brev((unsigned)idx) >> (32 - LOGL));
        v[q] = a[r];
    }
    __syncwarp();
#pragma unroll
    for (int q = 0; q < NPT; q++) a[lane + (q << 5)] = v[q];
    __syncwarp();
#pragma unroll
    for (int s = 1; s <= LOGL; s++) {
        const int half = 1 << (s - 1);
#pragma unroll
        for (int t = 0; t < (L >> 6); t++) {
            int j = lane + (t << 5);
            int pos = j & (half - 1);
            int i0 = ((j >> (s - 1)) << s) + pos;
            int i1 = i0 + half;
            float2 w = tw[pos << (9 - s)];
            float wy = INV ? w.y : -w.y;
            float2 x0 = a[i0], x1 = a[i1];
            float tr = w.x * x1.x - wy * x1.y;
            float ti = w.x * x1.y + wy * x1.x;
            a[i0] = make_float2(x0.x + tr, x0.y + ti);
            a[i1] = make_float2(x0.x - tr, x0.y - ti);
        }
        __syncwarp();
    }
}

__global__ void k_init_tw() {
    int k = threadIdx.x;  // 256 threads
    double ang = 6.283185307179586476925286766559 * (double)k / 512.0;
    g_tw[k] = make_float2((float)cos(ang), (float)sin(ang));
}

// Pre-transpose + bit-reverse I: g_It[tile][n1*128 + e] = I[tile][brev7(e)*128 + n1]
__global__ void __launch_bounds__(256) k_trI(const float* __restrict__ I) {
    int tile = blockIdx.x;               // b*NCH + k, 98 tiles
    const float* src = I + (size_t)tile * 16384;
    float* dst = g_It + (size_t)tile * 16384;
    for (int idx = threadIdx.x; idx < 16384; idx += 256) {
        int n1 = idx >> 7, e = idx & 127;
        dst[idx] = src[brev7(e) * 128 + n1];   // coalesced write
    }
}

// fft2(x) pass 1: axis-1 transforms. 128 blocks x 256 threads (8 warps/cols).
__global__ void __launch_bounds__(256) k_init_cols(const float* __restrict__ xr,
                                                   const float* __restrict__ xi,
                                                   int nx) {
    __shared__ float2 sm[8 * 520 + 256];
    float2* tw = sm + 8 * 520;
    int tid = threadIdx.x, w = tid >> 5, lane = tid & 31;
    tw[tid] = g_tw[tid];
    __syncthreads();
    int b = blockIdx.x >> 6;
    int c0 = (blockIdx.x & 63) << 3;
    int col = c0 + w;
    float2* a = sm + w * 520;
#pragma unroll
    for (int q = 0; q < 16; q++) {
        int j = lane + (q << 5);
        int idx = clampi(b * 262144 + j * 512 + col, nx);
        a[j] = make_float2(xr[idx], xi[idx]);
    }
    __syncwarp();
    warp_fft<512, 9, false>(a, tw);
    __syncthreads();
    for (int e = tid; e < 4096; e += 256) {      // transposed coalesced store
        int t = e >> 3, ww = e & 7;
        g_T[((size_t)b * 512 + t) * 512 + c0 + ww] = sm[ww * 520 + t];
    }
}

// fft2(x) pass 2: axis-2 transforms -> g_xFT (unshifted). 128 blocks x 256.
__global__ void __launch_bounds__(256) k_init_rows() {
    __shared__ float2 sm[8 * 520 + 256];
    float2* tw = sm + 8 * 520;
    int tid = threadIdx.x, w = tid >> 5, lane = tid & 31;
    tw[tid] = g_tw[tid];
    __syncthreads();
    int b = blockIdx.x >> 6;
    int f = ((blockIdx.x & 63) << 3) + w;
    float2* a = sm + w * 520;
    const float2* src = g_T + ((size_t)b * 512 + f) * 512;
#pragma unroll
    for (int q = 0; q < 16; q++) { int u = lane + (q << 5); a[u] = src[u]; }
    __syncwarp();
    warp_fft<512, 9, false>(a, tw);
    float2* dst = g_xFT + (size_t)b * 262144 + (size_t)f * 512;
#pragma unroll
    for (int q = 0; q < 16; q++) { int u = lane + (q << 5); dst[u] = a[u]; }
}

// ---------------------------------------------------------------------------
// Chain: cluster of 8 blocks per batch, 512 threads (16 warps = one transform
// row per warp). Register FFTs; smem only for inter-phase transposes.
// ---------------------------------------------------------------------------
__global__ void __launch_bounds__(512, 1) __cluster_dims__(CL, 1, 1)
k_chain(const float* __restrict__ P, const int* __restrict__ Ns) {
    __shared__ float2 sm[16 * 132];
    int tid = threadIdx.x, w = tid >> 5, lane = tid & 31;
    int b = blockIdx.x >> 3;          // cluster index = batch
    int blk = blockIdx.x & 7;         // rank within cluster
    int rowbase = blk << 4;           // 16 rows/cols owned by this block
    float2* xft = g_xFT + (size_t)b * 262144;
    float2* Wb = g_W + (size_t)b * 16384;
    float2* W2b = g_W2 + (size_t)b * 16384;
    const float sA = 1.0f / 262144.0f;  // (1/128^2) * scale_fwd(=1/16)

    // per-lane twiddle registers (k-invariant)
    float2 T[7];
    T[0] = g_tw[lane * 4];
    T[1] = g_tw[(lane + 32) * 4];
    T[2] = g_tw[lane * 8];
    T[3] = g_tw[(lane & 15) * 16];
    T[4] = g_tw[(lane & 7) * 32];
    T[5] = g_tw[(lane & 3) * 64];
    T[6] = g_tw[(lane & 1) * 128];

    int myrow = rowbase + w;
    float2 v[4];

    for (int k = 0; k < NCH; k++) {
        int kxl = 192 + Ns[2 * k];
        int kyl = 192 + Ns[2 * k + 1];

        // ---- phase 1: window*P (ifftshift folded) -> row IFFT(DIF) -> g_W^T
        {
            int r = (myrow + 64) & 127;
            int u0 = (kxl + r + 256) & 511;
            const float2* xrow = xft + (size_t)u0 * 512;
            const float* prow = P + r * 128;
#pragma unroll
            for (int q = 0; q < 4; q++) {
                int j1 = (q << 5) + lane;
                int c = j1 ^ 64;
                int u1 = (kyl + c + 256) & 511;
                float2 xv = __ldcg(&xrow[u1]);
                float p = prow[c];
                v[q] = make_float2(xv.x * p, xv.y * p);
            }
            rdif128<true>(v, T, lane);
#pragma unroll
            for (int q = 0; q < 4; q++)           // park at TRUE n1 positions
                sm[w * 132 + brev7((q << 5) + lane)] = v[q];
            __syncthreads();
            for (int e = tid; e < 2048; e += 512) {   // g_W[n1][j0]
                int n1 = e >> 4, rl = e & 15;
                Wb[n1 * 128 + rowbase + rl] = sm[rl * 132 + n1];
            }
        }
        CLUSTER_SYNC();

        // ---- phase 2: col IFFT(DIF) -> nonlinearity -> col FFT(DIT) -> g_W2^T
        {
            const float2* src = Wb + (size_t)myrow * 128;
#pragma unroll
            for (int q = 0; q < 4; q++) v[q] = __ldcg(&src[(q << 5) + lane]);
            rdif128<true>(v, T, lane);            // -> bitrev(n0) layout
            const float* Ikt = g_It + ((size_t)(b * NCH + k) << 14) + myrow * 128;
#pragma unroll
            for (int q = 0; q < 4; q++) {         // It pre-brev'd: coalesced
                float Iv = Ikt[(q << 5) + lane];
                float vr = v[q].x * sA, vi = v[q].y * sA;
                float m = vr * vr + vi * vi - Iv;
                v[q] = make_float2(m * vr, m * vi);
            }
            rdit128<false>(v, T, lane);           // bitrev -> natural m0
#pragma unroll
            for (int q = 0; q < 4; q++)
                sm[w * 132 + (q << 5) + lane] = v[q];
            __syncthreads();
            for (int e = tid; e < 2048; e += 512) {   // g_W2[m0][n1]
                int m0 = e >> 4, rl = e & 15;
                W2b[m0 * 128 + rowbase + rl] = sm[rl * 132 + m0];
            }
        }
        CLUSTER_SYNC();

        // ---- phase 3: row FFT(DIF) -> patch = fftshift(F)*P; update xFT ----
        {
            const float2* src = W2b + (size_t)myrow * 128;
#pragma unroll
            for (int q = 0; q < 4; q++) v[q] = __ldcg(&src[(q << 5) + lane]);
            rdif128<false>(v, T, lane);           // -> bitrev(m1)
#pragma unroll
            for (int q = 0; q < 4; q++)           // bounce to natural order
                sm[w * 132 + brev7((q << 5) + lane)] = v[q];
            __syncwarp();
            int r = (myrow + 64) & 127;
            int u0 = (kxl + r + 256) & 511;
            int kb = k * NB + b;
            float2* patch_row = g_patch + (size_t)kb * 16384 + r * 128;
            float2* xrow = xft + (size_t)u0 * 512;
            const float* prow = P + r * 128;
#pragma unroll
            for (int q = 0; q < 4; q++) {
                int m1 = (q << 5) + lane;
                int c = m1 ^ 64;
                float2 f = sm[w * 132 + m1];
                float p = prow[c];
                float2 patch = make_float2(f.x * p, f.y * p);
                patch_row[c] = patch;
                int u1 = (kyl + c + 256) & 511;
                float2 xv = __ldcg(&xrow[u1]);
                xrow[u1] = make_float2(xv.x - 0.16f * patch.x,
                                       xv.y - 0.16f * patch.y);
            }
        }
        CLUSTER_SYNC();
    }
}

// Grad pass 1: sparse axis-1 IFFT (128 nonzero rows -> 512). 1568 blocks x 256.
__global__ void __launch_bounds__(256) k_grad1(const int* __restrict__ Ns, int nns) {
    __shared__ float2 sm[8 * 520 + 256];
    float2* tw = sm + 8 * 520;
    int tid = threadIdx.x, w = tid >> 5, lane = tid & 31;
    tw[tid] = g_tw[tid];
    __syncthreads();
    int kb = blockIdx.x >> 4;
    int k = kb >> 1;
    int c0 = (blockIdx.x & 15) << 3;
    int c = c0 + w;
    int kxl = 192 + Ns[clampi(2 * k, nns)];
    float2* a = sm + w * 520;
#pragma unroll
    for (int q = 0; q < 16; q++) a[lane + (q << 5)] = make_float2(0.f, 0.f);
    __syncwarp();
    for (int r = lane; r < 128; r += 32) {
        int u0 = (kxl + r + 256) & 511;
        a[u0] = g_patch[(size_t)kb * 16384 + r * 128 + c];
    }
    __syncwarp();
    warp_fft<512, 9, true>(a, tw);
    __syncthreads();
    for (int e = tid; e < 4096; e += 256) {
        int t = e >> 3, ww = e & 7;
        g_T[((size_t)kb * 512 + t) * 128 + c0 + ww] = sm[ww * 520 + t];
    }
}

// Grad pass 2: sparse axis-2 IFFT -> REAL PART only, scaled, to output.
__global__ void __launch_bounds__(256) k_grad2(const int* __restrict__ Ns, int nns,
                                               float* __restrict__ outf,
                                               int n_out) {
    __shared__ float2 sm[8 * 520 + 256];
    float2* tw = sm + 8 * 520;
    int tid = threadIdx.x, w = tid >> 5, lane = tid & 31;
    tw[tid] = g_tw[tid];
    __syncthreads();
    int kb = blockIdx.x >> 6;
    int t = ((blockIdx.x & 63) << 3) + w;
    int k = kb >> 1, b = kb & 1;
    int kyl = 192 + Ns[clampi(2 * k + 1, nns)];
    float2* a = sm + w * 520;
#pragma unroll
    for (int q = 0; q < 16; q++) a[lane + (q << 5)] = make_float2(0.f, 0.f);
    __syncwarp();
    const float2* src = g_T + ((size_t)kb * 512 + t) * 128;
    for (int c = lane; c < 128; c += 32) {
        int u1 = (kyl + c + 256) & 511;
        a[u1] = src[c];
    }
    __syncwarp();
    warp_fft<512, 9, true>(a, tw);
    const float s = 1.0f / 16384.0f;        // (1/512^2) * scale_bwd(=16)
    long long base = (((long long)b * NCH + k) * 512 + t) * 512;
#pragma unroll
    for (int q = 0; q < 16; q++) {
        int u = lane + (q << 5);
        long long idx = base + u;           // float32 element index
        if (idx < (long long)n_out) {
            outf[idx] = a[u].x * s;         // REAL part only
        }
    }
}

// ---------------------------------------------------------------------------
extern "C" void kernel_launch(void* const* d_in, const int* in_sizes, int n_in,
                              void* d_out, int out_size) {
    // Bind by element count. The two 524288 buffers: FIRST = x_real,
    // SECOND = x_imag (verified passing R10-R14).
    const float *xr = nullptr, *xi = nullptr, *P = nullptr, *I = nullptr;
    const int* Ns = nullptr;
    int nx = 0, nns = 0;
    for (int i = 0; i < n_in; i++) {
        int sz = in_sizes[i];
        if (sz == 524288) {
            if (!xr) { xr = (const float*)d_in[i]; nx = sz; }
            else if (!xi) xi = (const float*)d_in[i];
        } else if (sz == 16384) { P = (const float*)d_in[i]; }
        else if (sz == 1605632) { I = (const float*)d_in[i]; }
        else if (sz == 98)      { Ns = (const int*)d_in[i]; nns = sz; }
    }
    if (!xr || !xi || !P || !I || !Ns) return;
    float* outf = (float*)d_out;

    k_init_tw<<<1, 256>>>();
    k_trI<<<NB * NCH, 256>>>(I);
    k_init_cols<<<128, 256>>>(xr, xi, nx);
    k_init_rows<<<128, 256>>>();
    k_chain<<<NB * CL, 512>>>(P, Ns);         // 2 clusters of 8 blocks
    k_grad1<<<1568, 256>>>(Ns, nns);
    k_grad2<<<6272, 256>>>(Ns, nns, outf, out_size);
}

// round 16
// speedup vs baseline: 6.6532x; 1.6429x over previous
#include <cuda_runtime.h>

// ---------------------------------------------------------------------------
//   x:  [2, 512, 512] complex (separate real/imag f32 planes)
//   P:  [128, 128] f32;  I: [2, 49, 128, 128] f32;  Ns: [49, 2] int32
//   out: float32 [2, 49, 512, 512] = REAL PART of complex grads (25,690,112)
//
// Fourier-domain restructuring:
//   X = fft2(x) carried unshifted; step k touches only a 128x128 window:
//     X[u0,u1] -= MU*scale_bwd * patch  (0.16)
//   grads[k] = ifft2(ifftshift(Z_k)) * 16, Z_k sparse -> two deferred passes.
//
// R15->R16: grad passes use a register-resident 512-pt DIT FFT (16 float2 /
// lane, shuffle + register butterflies). Sparse inputs are gathered directly
// in bit-reversed order (free — gather was scattered anyway); outputs come
// out natural. grad2 needs no smem at all. Chain identical to R15 (passing).
// ---------------------------------------------------------------------------

#define NOBJ 512
#define MM   128
#define NCH  49
#define NB   2
#define CL   8        // chain blocks per cluster (= per batch)

__device__ float2 g_tw[256];                         // exp(+2*pi*i*k/512), k<256
__device__ float2 g_xFT[NB * NOBJ * NOBJ];           // 4 MB
__device__ float2 g_patch[NCH * NB * MM * MM];       // 12.8 MB  [kb][r][c]
__device__ float2 g_T[(size_t)NCH * NB * NOBJ * MM]; // 51.4 MB  [kb][t][c]
__device__ float2 g_W[NB * MM * MM];                 // step ping  [b][n1][j0]
__device__ float2 g_W2[NB * MM * MM];                // step pong  [b][m0][n1]
__device__ float  g_It[(size_t)NB * NCH * MM * MM];  // 6.4 MB: I transposed+brev

__device__ __forceinline__ int clampi(int i, int n) {
    return i < 0 ? 0 : (i >= n ? n - 1 : i);
}
__device__ __forceinline__ int brev7(int x) {
    return (int)(__brev((unsigned)x) >> 25);
}
__device__ __forceinline__ int brev9(int x) {
    return (int)(__brev((unsigned)x) >> 23);
}

#define CLUSTER_SYNC() do { \
    asm volatile("barrier.cluster.arrive.aligned;" ::: "memory"); \
    asm volatile("barrier.cluster.wait.aligned;" ::: "memory"); } while (0)

// ---------------------------------------------------------------------------
// Butterfly primitives (R15-proven numerics).
// ---------------------------------------------------------------------------
template <bool INV>
__device__ __forceinline__ void dif_bfly(float2& x0, float2& x1, float2 w) {
    float wy = INV ? w.y : -w.y;
    float dx = x0.x - x1.x, dy = x0.y - x1.y;
    x0.x += x1.x; x0.y += x1.y;
    x1.x = w.x * dx - wy * dy;
    x1.y = w.x * dy + wy * dx;
}
template <bool INV>
__device__ __forceinline__ void dit_bfly(float2& x0, float2& x1, float2 w) {
    float wy = INV ? w.y : -w.y;
    float tx = w.x * x1.x - wy * x1.y;
    float ty = w.x * x1.y + wy * x1.x;
    x1.x = x0.x - tx; x1.y = x0.y - ty;
    x0.x += tx; x0.y += ty;
}
template <bool INV>
__device__ __forceinline__ void dif_shfl(float2 v[4], int half, float2 w, int lane) {
    float wy = INV ? w.y : -w.y;
    bool up = (lane & half) == 0;
#pragma unroll
    for (int q = 0; q < 4; q++) {
        float ox = __shfl_xor_sync(0xffffffffu, v[q].x, half);
        float oy = __shfl_xor_sync(0xffffffffu, v[q].y, half);
        float ax = v[q].x + ox, ay = v[q].y + oy;
        float dx = ox - v[q].x, dy = oy - v[q].y;
        float bx = w.x * dx - wy * dy, by = w.x * dy + wy * dx;
        v[q].x = up ? ax : bx;
        v[q].y = up ? ay : by;
    }
}
template <bool INV>
__device__ __forceinline__ void dit_shfl(float2 v[4], int half, float2 w, int lane) {
    float wy = INV ? w.y : -w.y;
    bool up = (lane & half) == 0;
#pragma unroll
    for (int q = 0; q < 4; q++) {
        float ox = __shfl_xor_sync(0xffffffffu, v[q].x, half);
        float oy = __shfl_xor_sync(0xffffffffu, v[q].y, half);
        float sx = up ? ox : v[q].x;
        float sy = up ? oy : v[q].y;
        float tx = w.x * sx - wy * sy;
        float ty = w.x * sy + wy * sx;
        float rx = up ? (v[q].x + tx) : (ox - tx);
        float ry = up ? (v[q].y + ty) : (oy - ty);
        v[q].x = rx; v[q].y = ry;
    }
}
template <bool INV>
__device__ __forceinline__ void dit_shfl16(float2 v[16], int half, float2 w, int lane) {
    float wy = INV ? w.y : -w.y;
    bool up = (lane & half) == 0;
#pragma unroll
    for (int q = 0; q < 16; q++) {
        float ox = __shfl_xor_sync(0xffffffffu, v[q].x, half);
        float oy = __shfl_xor_sync(0xffffffffu, v[q].y, half);
        float sx = up ? ox : v[q].x;
        float sy = up ? oy : v[q].y;
        float tx = w.x * sx - wy * sy;
        float ty = w.x * sy + wy * sx;
        float rx = up ? (v[q].x + tx) : (ox - tx);
        float ry = up ? (v[q].y + ty) : (oy - ty);
        v[q].x = rx; v[q].y = ry;
    }
}

// 128-pt register FFTs (R15-proven). e = q*32+lane.
template <bool INV>
__device__ __forceinline__ void rdif128(float2 v[4], const float2* T, int lane) {
    dif_bfly<INV>(v[0], v[2], T[0]);
    dif_bfly<INV>(v[1], v[3], T[1]);
    dif_bfly<INV>(v[0], v[1], T[2]);
    dif_bfly<INV>(v[2], v[3], T[2]);
    dif_shfl<INV>(v, 16, T[3], lane);
    dif_shfl<INV>(v, 8,  T[4], lane);
    dif_shfl<INV>(v, 4,  T[5], lane);
    dif_shfl<INV>(v, 2,  T[6], lane);
    dif_shfl<INV>(v, 1,  make_float2(1.f, 0.f), lane);
}
template <bool INV>
__device__ __forceinline__ void rdit128(float2 v[4], const float2* T, int lane) {
    dit_shfl<INV>(v, 1,  make_float2(1.f, 0.f), lane);
    dit_shfl<INV>(v, 2,  T[6], lane);
    dit_shfl<INV>(v, 4,  T[5], lane);
    dit_shfl<INV>(v, 8,  T[4], lane);
    dit_shfl<INV>(v, 16, T[3], lane);
    dit_bfly<INV>(v[0], v[1], T[2]);
    dit_bfly<INV>(v[2], v[3], T[2]);
    dit_bfly<INV>(v[0], v[2], T[0]);
    dit_bfly<INV>(v[1], v[3], T[1]);
}

// 512-pt register DIT: bitrev input (position p=q*32+lane holds input element
// brev9(p)), natural output. Twiddle schedule mirrors the R10-proven smem DIT:
// stage s: half=2^(s-1), tw[(p & (half-1)) << (9-s)].
template <bool INV>
__device__ __forceinline__ void rdit512(float2 v[16], const float2* tw, int lane) {
    dit_shfl16<INV>(v, 1,  make_float2(1.f, 0.f), lane);     // s=1
    dit_shfl16<INV>(v, 2,  tw[(lane & 1) * 128], lane);      // s=2
    dit_shfl16<INV>(v, 4,  tw[(lane & 3) * 64], lane);       // s=3
    dit_shfl16<INV>(v, 8,  tw[(lane & 7) * 32], lane);       // s=4
    dit_shfl16<INV>(v, 16, tw[(lane & 15) * 16], lane);      // s=5
    {   // s=6: half=32, pairs (q, q+1), q even; pos = lane
        float2 w = tw[lane * 8];
#pragma unroll
        for (int q = 0; q < 16; q += 2) dit_bfly<INV>(v[q], v[q + 1], w);
    }
    {   // s=7: half=64, pairs (q, q+2); pos = (q&1)*32 + lane
        float2 w0 = tw[lane * 4];
        float2 w1 = tw[(32 + lane) * 4];
#pragma unroll
        for (int qb = 0; qb < 16; qb += 4) {
            dit_bfly<INV>(v[qb],     v[qb + 2], w0);
            dit_bfly<INV>(v[qb + 1], v[qb + 3], w1);
        }
    }
    {   // s=8: half=128, pairs (q, q+4); pos = (q&3)*32 + lane
        float2 w0 = tw[lane * 2];
        float2 w1 = tw[(32 + lane) * 2];
        float2 w2 = tw[(64 + lane) * 2];
        float2 w3 = tw[(96 + lane) * 2];
#pragma unroll
        for (int qb = 0; qb < 16; qb += 8) {
            dit_bfly<INV>(v[qb],     v[qb + 4], w0);
            dit_bfly<INV>(v[qb + 1], v[qb + 5], w1);
            dit_bfly<INV>(v[qb + 2], v[qb + 6], w2);
            dit_bfly<INV>(v[qb + 3], v[qb + 7], w3);
        }
    }
    {   // s=9: half=256, pairs (q, q+8); pos = q*32 + lane
#pragma unroll
        for (int q = 0; q < 8; q++) {
            float2 w = tw[q * 32 + lane];
            dit_bfly<INV>(v[q], v[q + 8], w);
        }
    }
}

// smem warp_fft (natural->natural) — still used by init kernels (R10-proven).
template <int L, int LOGL, bool INV>
__device__ __forceinline__ void warp_fft(float2* a, const float2* tw) {
    const int lane = threadIdx.x & 31;
    constexpr int NPT = L / 32;
    float2 v[NPT];
#pragma unroll
    for (int q = 0; q < NPT; q++) {
        int idx = lane + (q << 5);
        int r = (int)(__brev((unsigned)idx) >> (32 - LOGL));
        v[q] = a[r];
    }
    __syncwarp();
#pragma unroll
    for (int q = 0; q < NPT; q++) a[lane + (q << 5)] = v[q];
    __syncwarp();
#pragma unroll
    for (int s = 1; s <= LOGL; s++) {
        const int half = 1 << (s - 1);
#pragma unroll
        for (int t = 0; t < (L >> 6); t++) {
            int j = lane + (t << 5);
            int pos = j & (half - 1);
            int i0 = ((j >> (s - 1)) << s) + pos;
            int i1 = i0 + half;
            float2 w = tw[pos << (9 - s)];
            float wy = INV ? w.y : -w.y;
            float2 x0 = a[i0], x1 = a[i1];
            float tr = w.x * x1.x - wy * x1.y;
            float ti = w.x * x1.y + wy * x1.x;
            a[i0] = make_float2(x0.x + tr, x0.y + ti);
            a[i1] = make_float2(x0.x - tr, x0.y - ti);
        }
        __syncwarp();
    }
}

__global__ void k_init_tw() {
    int k = threadIdx.x;  // 256 threads
    double ang = 6.283185307179586476925286766559 * (double)k / 512.0;
    g_tw[k] = make_float2((float)cos(ang), (float)sin(ang));
}

// Pre-transpose + bit-reverse I for the chain's phase-2 gather.
__global__ void __launch_bounds__(256) k_trI(const float* __restrict__ I) {
    int tile = blockIdx.x;               // b*NCH + k, 98 tiles
    const float* src = I + (size_t)tile * 16384;
    float* dst = g_It + (size_t)tile * 16384;
    for (int idx = threadIdx.x; idx < 16384; idx += 256) {
        int n1 = idx >> 7, e = idx & 127;
        dst[idx] = src[brev7(e) * 128 + n1];
    }
}

// fft2(x) pass 1: axis-1 transforms. 128 blocks x 256 threads.
__global__ void __launch_bounds__(256) k_init_cols(const float* __restrict__ xr,
                                                   const float* __restrict__ xi,
                                                   int nx) {
    __shared__ float2 sm[8 * 520 + 256];
    float2* tw = sm + 8 * 520;
    int tid = threadIdx.x, w = tid >> 5, lane = tid & 31;
    tw[tid] = g_tw[tid];
    __syncthreads();
    int b = blockIdx.x >> 6;
    int c0 = (blockIdx.x & 63) << 3;
    int col = c0 + w;
    float2* a = sm + w * 520;
#pragma unroll
    for (int q = 0; q < 16; q++) {
        int j = lane + (q << 5);
        int idx = clampi(b * 262144 + j * 512 + col, nx);
        a[j] = make_float2(xr[idx], xi[idx]);
    }
    __syncwarp();
    warp_fft<512, 9, false>(a, tw);
    __syncthreads();
    for (int e = tid; e < 4096; e += 256) {
        int t = e >> 3, ww = e & 7;
        g_T[((size_t)b * 512 + t) * 512 + c0 + ww] = sm[ww * 520 + t];
    }
}

// fft2(x) pass 2: axis-2 transforms -> g_xFT. 128 blocks x 256.
__global__ void __launch_bounds__(256) k_init_rows() {
    __shared__ float2 sm[8 * 520 + 256];
    float2* tw = sm + 8 * 520;
    int tid = threadIdx.x, w = tid >> 5, lane = tid & 31;
    tw[tid] = g_tw[tid];
    __syncthreads();
    int b = blockIdx.x >> 6;
    int f = ((blockIdx.x & 63) << 3) + w;
    float2* a = sm + w * 520;
    const float2* src = g_T + ((size_t)b * 512 + f) * 512;
#pragma unroll
    for (int q = 0; q < 16; q++) { int u = lane + (q << 5); a[u] = src[u]; }
    __syncwarp();
    warp_fft<512, 9, false>(a, tw);
    float2* dst = g_xFT + (size_t)b * 262144 + (size_t)f * 512;
#pragma unroll
    for (int q = 0; q < 16; q++) { int u = lane + (q << 5); dst[u] = a[u]; }
}

// ---------------------------------------------------------------------------
// Chain: identical to R15 (passing). Cluster of 8 blocks per batch.
// ---------------------------------------------------------------------------
__global__ void __launch_bounds__(512, 1) __cluster_dims__(CL, 1, 1)
k_chain(const float* __restrict__ P, const int* __restrict__ Ns) {
    __shared__ float2 sm[16 * 132];
    int tid = threadIdx.x, w = tid >> 5, lane = tid & 31;
    int b = blockIdx.x >> 3;
    int blk = blockIdx.x & 7;
    int rowbase = blk << 4;
    float2* xft = g_xFT + (size_t)b * 262144;
    float2* Wb = g_W + (size_t)b * 16384;
    float2* W2b = g_W2 + (size_t)b * 16384;
    const float sA = 1.0f / 262144.0f;

    float2 T[7];
    T[0] = g_tw[lane * 4];
    T[1] = g_tw[(lane + 32) * 4];
    T[2] = g_tw[lane * 8];
    T[3] = g_tw[(lane & 15) * 16];
    T[4] = g_tw[(lane & 7) * 32];
    T[5] = g_tw[(lane & 3) * 64];
    T[6] = g_tw[(lane & 1) * 128];

    int myrow = rowbase + w;
    float2 v[4];

    for (int k = 0; k < NCH; k++) {
        int kxl = 192 + Ns[2 * k];
        int kyl = 192 + Ns[2 * k + 1];

        {   // phase 1
            int r = (myrow + 64) & 127;
            int u0 = (kxl + r + 256) & 511;
            const float2* xrow = xft + (size_t)u0 * 512;
            const float* prow = P + r * 128;
#pragma unroll
            for (int q = 0; q < 4; q++) {
                int j1 = (q << 5) + lane;
                int c = j1 ^ 64;
                int u1 = (kyl + c + 256) & 511;
                float2 xv = __ldcg(&xrow[u1]);
                float p = prow[c];
                v[q] = make_float2(xv.x * p, xv.y * p);
            }
            rdif128<true>(v, T, lane);
#pragma unroll
            for (int q = 0; q < 4; q++)
                sm[w * 132 + brev7((q << 5) + lane)] = v[q];
            __syncthreads();
            for (int e = tid; e < 2048; e += 512) {
                int n1 = e >> 4, rl = e & 15;
                Wb[n1 * 128 + rowbase + rl] = sm[rl * 132 + n1];
            }
        }
        CLUSTER_SYNC();

        {   // phase 2
            const float2* src = Wb + (size_t)myrow * 128;
#pragma unroll
            for (int q = 0; q < 4; q++) v[q] = __ldcg(&src[(q << 5) + lane]);
            rdif128<true>(v, T, lane);
            const float* Ikt = g_It + ((size_t)(b * NCH + k) << 14) + myrow * 128;
#pragma unroll
            for (int q = 0; q < 4; q++) {
                float Iv = Ikt[(q << 5) + lane];
                float vr = v[q].x * sA, vi = v[q].y * sA;
                float m = vr * vr + vi * vi - Iv;
                v[q] = make_float2(m * vr, m * vi);
            }
            rdit128<false>(v, T, lane);
#pragma unroll
            for (int q = 0; q < 4; q++)
                sm[w * 132 + (q << 5) + lane] = v[q];
            __syncthreads();
            for (int e = tid; e < 2048; e += 512) {
                int m0 = e >> 4, rl = e & 15;
                W2b[m0 * 128 + rowbase + rl] = sm[rl * 132 + m0];
            }
        }
        CLUSTER_SYNC();

        {   // phase 3
            const float2* src = W2b + (size_t)myrow * 128;
#pragma unroll
            for (int q = 0; q < 4; q++) v[q] = __ldcg(&src[(q << 5) + lane]);
            rdif128<false>(v, T, lane);
#pragma unroll
            for (int q = 0; q < 4; q++)
                sm[w * 132 + brev7((q << 5) + lane)] = v[q];
            __syncwarp();
            int r = (myrow + 64) & 127;
            int u0 = (kxl + r + 256) & 511;
            int kb = k * NB + b;
            float2* patch_row = g_patch + (size_t)kb * 16384 + r * 128;
            float2* xrow = xft + (size_t)u0 * 512;
            const float* prow = P + r * 128;
#pragma unroll
            for (int q = 0; q < 4; q++) {
                int m1 = (q << 5) + lane;
                int c = m1 ^ 64;
                float2 f = sm[w * 132 + m1];
                float p = prow[c];
                float2 patch = make_float2(f.x * p, f.y * p);
                patch_row[c] = patch;
                int u1 = (kyl + c + 256) & 511;
                float2 xv = __ldcg(&xrow[u1]);
                xrow[u1] = make_float2(xv.x - 0.16f * patch.x,
                                       xv.y - 0.16f * patch.y);
            }
        }
        CLUSTER_SYNC();
    }
}

// ---------------------------------------------------------------------------
// Grad pass 1: register 512-pt DIT per warp (column c). Sparse input gathered
// in bitrev order (free); natural output parked to smem -> transposed g_T.
// 1568 blocks x 256 (8 warps = 8 columns).
// ---------------------------------------------------------------------------
__global__ void __launch_bounds__(256) k_grad1(const int* __restrict__ Ns, int nns) {
    __shared__ float2 smem[8 * 520 + 256];
    float2* tw = smem + 8 * 520;
    int tid = threadIdx.x, w = tid >> 5, lane = tid & 31;
    tw[tid] = g_tw[tid];
    __syncthreads();
    int kb = blockIdx.x >> 4;
    int k = kb >> 1;
    int c0 = (blockIdx.x & 15) << 3;
    int c = c0 + w;
    int off0 = (192 + Ns[clampi(2 * k, nns)] + 256) & 511;   // nonzero at (off0+r)&511
    const float2* patch = g_patch + (size_t)kb * 16384;

    float2 v[16];
#pragma unroll
    for (int q = 0; q < 16; q++) {
        int p = (q << 5) + lane;
        int j = brev9(p);                    // input element index at position p
        int r = (j - off0) & 511;
        v[q] = (r < 128) ? patch[r * 128 + c] : make_float2(0.f, 0.f);
    }
    rdit512<true>(v, tw, lane);              // natural output t = q*32+lane
    float2* a = smem + w * 520;
#pragma unroll
    for (int q = 0; q < 16; q++) a[(q << 5) + lane] = v[q];
    __syncthreads();
    for (int e = tid; e < 4096; e += 256) {
        int t = e >> 3, ww = e & 7;
        g_T[((size_t)kb * 512 + t) * 128 + c0 + ww] = smem[ww * 520 + t];
    }
}

// ---------------------------------------------------------------------------
// Grad pass 2: register 512-pt DIT per warp (row t). Sparse input gathered in
// bitrev order from the g_T row (L1-resident); natural output -> coalesced
// real-part store. No smem except the twiddle table. 6272 blocks x 256.
// ---------------------------------------------------------------------------
__global__ void __launch_bounds__(256) k_grad2(const int* __restrict__ Ns, int nns,
                                               float* __restrict__ outf,
                                               int n_out) {
    __shared__ float2 tw[256];
    int tid = threadIdx.x, w = tid >> 5, lane = tid & 31;
    tw[tid] = g_tw[tid];
    __syncthreads();
    int kb = blockIdx.x >> 6;
    int t = ((blockIdx.x & 63) << 3) + w;
    int k = kb >> 1, b = kb & 1;
    int off1 = (192 + Ns[clampi(2 * k + 1, nns)] + 256) & 511;
    const float2* src = g_T + ((size_t)kb * 512 + t) * 128;

    float2 v[16];
#pragma unroll
    for (int q = 0; q < 16; q++) {
        int p = (q << 5) + lane;
        int j = brev9(p);
        int c = (j - off1) & 511;
        v[q] = (c < 128) ? src[c] : make_float2(0.f, 0.f);
    }
    rdit512<true>(v, tw, lane);              // natural output u = q*32+lane

    const float s = 1.0f / 16384.0f;         // (1/512^2) * scale_bwd(=16)
    long long base = (((long long)b * NCH + k) * 512 + t) * 512;
#pragma unroll
    for (int q = 0; q < 16; q++) {
        long long idx = base + (q << 5) + lane;
        if (idx < (long long)n_out) {
            outf[idx] = v[q].x * s;          // REAL part only
        }
    }
}

// ---------------------------------------------------------------------------
extern "C" void kernel_launch(void* const* d_in, const int* in_sizes, int n_in,
                              void* d_out, int out_size) {
    // Bind by element count. The two 524288 buffers: FIRST = x_real,
    // SECOND = x_imag (verified passing R10-R15).
    const float *xr = nullptr, *xi = nullptr, *P = nullptr, *I = nullptr;
    const int* Ns = nullptr;
    int nx = 0, nns = 0;
    for (int i = 0; i < n_in; i++) {
        int sz = in_sizes[i];
        if (sz == 524288) {
            if (!xr) { xr = (const float*)d_in[i]; nx = sz; }
            else if (!xi) xi = (const float*)d_in[i];
        } else if (sz == 16384) { P = (const float*)d_in[i]; }
        else if (sz == 1605632) { I = (const float*)d_in[i]; }
        else if (sz == 98)      { Ns = (const int*)d_in[i]; nns = sz; }
    }
    if (!xr || !xi || !P || !I || !Ns) return;
    float* outf = (float*)d_out;

    k_init_tw<<<1, 256>>>();
    k_trI<<<NB * NCH, 256>>>(I);
    k_init_cols<<<128, 256>>>(xr, xi, nx);
    k_init_rows<<<128, 256>>>();
    k_chain<<<NB * CL, 512>>>(P, Ns);         // 2 clusters of 8 blocks
    k_grad1<<<1568, 256>>>(Ns, nns);
    k_grad2<<<6272, 256>>>(Ns, nns, outf, out_size);
}